// round 1
// baseline (speedup 1.0000x reference)
#include <cuda_runtime.h>
#include <cuda_fp16.h>
#include <cstdint>

// Problem constants
#define NBLK 64      // number of block rows/cols
#define P    256     // block size
#define ROWS 4096    // batch
#define KDIM 768     // 3*P contraction per output block-row
#define OUTW 16384   // NBLK*P
#define KT   32      // k per mainloop stage
#define SROW 40      // smem halves per row (32 data + 8 pad; stride 80B -> conflict-free)

// fp16 band-weight scratch: [i][n(=out col q)][k(=3*P gathered p)]
__device__ __align__(16) __half g_Wcvt[(size_t)NBLK * P * KDIM];

// ---------------------------------------------------------------------------
// Weight gather + fp32->fp16 convert.  B[k][n] = W[n][k] so storing source
// row-major [q][p] blocks contiguously along k gives exactly the [n][k]
// layout the GEMM's B tiles want.
// ---------------------------------------------------------------------------
__global__ void cvt_w_kernel(const float* __restrict__ Wd, const float* __restrict__ Wu,
                             const float* __restrict__ Wl, const float* __restrict__ Wtr,
                             const float* __restrict__ Wbl) {
    int idx = blockIdx.x * blockDim.x + threadIdx.x;   // total = 64*256*768, grid exact
    int k = idx % KDIM;
    int n = (idx / KDIM) % P;
    int i = idx / (KDIM * P);
    int chunk = k >> 8;      // 0: x_{i-1}, 1: x_i, 2: x_{i+1}
    int p = k & 255;
    float v;
    if (chunk == 0)      v = (i == 0)        ? Wtr[n * P + p] : Wl[(size_t)(i - 1) * P * P + n * P + p];
    else if (chunk == 1) v = Wd[(size_t)i * P * P + n * P + p];
    else                 v = (i == NBLK - 1) ? Wbl[n * P + p] : Wu[(size_t)i * P * P + n * P + p];
    g_Wcvt[idx] = __float2half_rn(v);
}

// ---------------------------------------------------------------------------
// GEMM: for each block-row i, out[:, i*256 : (i+1)*256] =
//   [x_{i-1} | x_i | x_{i+1}] (fp16) @ Wcvt[i]^T   with fp32 accumulate.
// CTA tile 128(M) x 128(N), K loop 768 in steps of 32, double-buffered smem.
// 8 warps in a 4x2 (M x N) grid, each warp 32x64 via m16n8k16 mma.sync.
// ---------------------------------------------------------------------------
__global__ void __launch_bounds__(256, 1)
gemm_kernel(const float* __restrict__ x, float* __restrict__ out) {
    __shared__ __align__(16) __half sA[2][128 * SROW];
    __shared__ __align__(16) __half sB[2][128 * SROW];

    const int tid   = threadIdx.x;
    const int mtile = blockIdx.x;   // 0..31
    const int ntile = blockIdx.y;   // 0..1
    const int ib    = blockIdx.z;   // 0..63 (block row)

    // A global load mapping: 128x32 floats, 4 float4 per thread
    const int a_row0 = tid >> 3;          // 0..31 (4 passes of 32 rows)
    const int a_col  = (tid & 7) * 4;     // 0,4,..,28

    const int warp = tid >> 5;
    const int lane = tid & 31;
    const int mw = warp >> 1;             // 0..3  -> M offset mw*32
    const int nw = warp & 1;              // 0..1  -> N offset nw*64
    const int g  = lane >> 2;             // groupID
    const int tg = lane & 3;              // threadID in group
    const int lr = (lane & 7) + ((lane >> 3) & 1) * 8;  // ldmatrix row within 16
    const int lk = (lane >> 4) & 1;                     // ldmatrix k-half (+16B)

    const int brow0 = ntile * 128;

    float4 aReg[4];
    uint4  bReg[2];
    float acc[2][8][4];
#pragma unroll
    for (int a = 0; a < 2; a++)
#pragma unroll
        for (int b = 0; b < 8; b++)
#pragma unroll
            for (int c = 0; c < 4; c++) acc[a][b][c] = 0.f;

    auto load_a = [&](int kt) {
        int chunk = kt >> 3;                            // 8 iters of 32 cover one 256 block
        int bc = (ib + chunk + NBLK - 1) & (NBLK - 1);  // periodic neighbor block col
        const float* base = x + (size_t)(mtile * 128) * OUTW + bc * P + (kt & 7) * KT + a_col;
#pragma unroll
        for (int p2 = 0; p2 < 4; p2++)
            aReg[p2] = *(const float4*)(base + (size_t)(a_row0 + p2 * 32) * OUTW);
    };
    auto store_a = [&](int buf) {
#pragma unroll
        for (int p2 = 0; p2 < 4; p2++) {
            __half2* d = (__half2*)&sA[buf][(a_row0 + p2 * 32) * SROW + a_col];
            d[0] = __float22half2_rn(make_float2(aReg[p2].x, aReg[p2].y));
            d[1] = __float22half2_rn(make_float2(aReg[p2].z, aReg[p2].w));
        }
    };
    auto load_b = [&](int kt) {
#pragma unroll
        for (int j = 0; j < 2; j++) {
            int c2 = tid + 256 * j;         // 0..511 segments of 16B
            int r2 = c2 >> 2, s2 = c2 & 3;  // row 0..127, seg 0..3
            bReg[j] = *(const uint4*)&g_Wcvt[(size_t)(ib * P + brow0 + r2) * KDIM + kt * KT + s2 * 8];
        }
    };
    auto store_b = [&](int buf) {
#pragma unroll
        for (int j = 0; j < 2; j++) {
            int c2 = tid + 256 * j;
            int r2 = c2 >> 2, s2 = c2 & 3;
            *(uint4*)&sB[buf][r2 * SROW + s2 * 8] = bReg[j];   // 80B row stride keeps 16B align
        }
    };
    auto mma_stage = [&](int buf) {
        uint32_t sa_base = (uint32_t)__cvta_generic_to_shared(&sA[buf][0]);
#pragma unroll
        for (int ks = 0; ks < 2; ks++) {     // two k16 steps per KT=32
            uint32_t af[2][4];
#pragma unroll
            for (int mt2 = 0; mt2 < 2; mt2++) {
                uint32_t addr = sa_base +
                    (uint32_t)((mw * 32 + mt2 * 16 + lr) * (SROW * 2) + lk * 16 + ks * 32);
                asm volatile("ldmatrix.sync.aligned.m8n8.x4.shared.b16 {%0,%1,%2,%3}, [%4];"
                             : "=r"(af[mt2][0]), "=r"(af[mt2][1]), "=r"(af[mt2][2]), "=r"(af[mt2][3])
                             : "r"(addr));
            }
            uint32_t bf[8][2];
#pragma unroll
            for (int nt2 = 0; nt2 < 8; nt2++) {
                const uint32_t* bp =
                    (const uint32_t*)&sB[buf][(nw * 64 + nt2 * 8 + g) * SROW + ks * 16 + tg * 2];
                bf[nt2][0] = bp[0];   // k = ks*16 + tg*2, tg*2+1
                bf[nt2][1] = bp[4];   // +8 halves (k+8, k+9)
            }
#pragma unroll
            for (int mt2 = 0; mt2 < 2; mt2++)
#pragma unroll
                for (int nt2 = 0; nt2 < 8; nt2++)
                    asm volatile(
                        "mma.sync.aligned.m16n8k16.row.col.f32.f16.f16.f32 "
                        "{%0,%1,%2,%3}, {%4,%5,%6,%7}, {%8,%9}, {%0,%1,%2,%3};"
                        : "+f"(acc[mt2][nt2][0]), "+f"(acc[mt2][nt2][1]),
                          "+f"(acc[mt2][nt2][2]), "+f"(acc[mt2][nt2][3])
                        : "r"(af[mt2][0]), "r"(af[mt2][1]), "r"(af[mt2][2]), "r"(af[mt2][3]),
                          "r"(bf[nt2][0]), "r"(bf[nt2][1]));
        }
    };

    // ---- mainloop: 24 stages, register-prefetch double buffer ----
    load_a(0); load_b(0);
    store_a(0); store_b(0);
    __syncthreads();

#pragma unroll 2
    for (int kt = 0; kt < 24; kt++) {
        const int cur = kt & 1, nxt = cur ^ 1;
        if (kt < 23) { load_a(kt + 1); load_b(kt + 1); }   // overlap global lat with math
        mma_stage(cur);
        if (kt < 23) { store_a(nxt); store_b(nxt); }
        __syncthreads();
    }

    // ---- epilogue: fp32 stores, float2 vectorized ----
#pragma unroll
    for (int mt2 = 0; mt2 < 2; mt2++) {
#pragma unroll
        for (int nt2 = 0; nt2 < 8; nt2++) {
            int row = mtile * 128 + mw * 32 + mt2 * 16 + g;
            int col = ib * P + brow0 + nw * 64 + nt2 * 8 + tg * 2;
            *(float2*)&out[(size_t)row * OUTW + col] =
                make_float2(acc[mt2][nt2][0], acc[mt2][nt2][1]);
            *(float2*)&out[(size_t)(row + 8) * OUTW + col] =
                make_float2(acc[mt2][nt2][2], acc[mt2][nt2][3]);
        }
    }
}

extern "C" void kernel_launch(void* const* d_in, const int* in_sizes, int n_in,
                              void* d_out, int out_size) {
    const float* x   = (const float*)d_in[0];
    const float* Wd  = (const float*)d_in[1];
    const float* Wu  = (const float*)d_in[2];
    const float* Wl  = (const float*)d_in[3];
    const float* Wtr = (const float*)d_in[4];
    const float* Wbl = (const float*)d_in[5];
    float* out = (float*)d_out;

    // 1) gather + convert weights to fp16 band layout (deterministic, every call)
    cvt_w_kernel<<<(NBLK * P * KDIM) / 256, 256>>>(Wd, Wu, Wl, Wtr, Wbl);

    // 2) batched band GEMM; i (z) slowest so each wave reuses ~5 x-block slices in L2
    dim3 grid(32, 2, NBLK);
    gemm_kernel<<<grid, 256>>>(x, out);
}

// round 4
// speedup vs baseline: 1.5695x; 1.5695x over previous
#include <cuda_runtime.h>
#include <cuda_fp16.h>
#include <cstdint>

// ---------------- problem constants ----------------
#define NBLK 64
#define P    256
#define ROWS 4096
#define KDIM 768         // 3*P
#define OUTW 16384       // NBLK*P
#define KT   64          // k halves per stage (128B rows, SW128-style swizzle)
#define NSTAGE_K 12      // KDIM / KT
#define NBUF 3           // pipeline depth

// smem: per stage A 16KB + B 16KB
#define STG_BYTES 32768
#define SM_A(s) ((s) * STG_BYTES)
#define SM_B(s) ((s) * STG_BYTES + 16384)
#define SM_TOTAL (NBUF * STG_BYTES)   // 96KB

// fp16 band weights [i][n=256][k=768] and fp16 copy of x
__device__ __align__(16) __half g_Wcvt[(size_t)NBLK * P * KDIM];
__device__ __align__(16) __half g_Xh[(size_t)ROWS * OUTW];

__device__ __forceinline__ uint32_t cvt2(float a, float b) {
    __half2 h = __float22half2_rn(make_float2(a, b));
    return *(uint32_t*)&h;
}
__device__ __forceinline__ void cp16(uint32_t dst, const void* src) {
    asm volatile("cp.async.cg.shared.global [%0], [%1], 16;" :: "r"(dst), "l"(src));
}

// ---------------------------------------------------------------------------
// Weight gather + fp32->fp16 convert into band layout [i][n][k].
// ---------------------------------------------------------------------------
__global__ void cvt_w_kernel(const float* __restrict__ Wd, const float* __restrict__ Wu,
                             const float* __restrict__ Wl, const float* __restrict__ Wtr,
                             const float* __restrict__ Wbl) {
    int idx = blockIdx.x * blockDim.x + threadIdx.x;   // 64*256*384 (half2 units)
    int k2 = idx % (KDIM / 2);
    int n  = (idx / (KDIM / 2)) % P;
    int i  = idx / ((KDIM / 2) * P);
    int kg = k2 * 2;
    int chunk = kg >> 8;
    int p = kg & 255;
    const float* W;
    if (chunk == 0)      W = (i == 0)        ? Wtr : Wl + (size_t)(i - 1) * P * P;
    else if (chunk == 1) W = Wd + (size_t)i * P * P;
    else                 W = (i == NBLK - 1) ? Wbl : Wu + (size_t)i * P * P;
    ((uint32_t*)g_Wcvt)[idx] = cvt2(W[n * P + p], W[n * P + p + 1]);
}

// ---------------------------------------------------------------------------
// x fp32 -> fp16 (one pass)
// ---------------------------------------------------------------------------
__global__ void cvt_x_kernel(const float* __restrict__ x) {
    size_t i = ((size_t)blockIdx.x * 256 + threadIdx.x) * 8;
    float4 f0 = *(const float4*)(x + i);
    float4 f1 = *(const float4*)(x + i + 4);
    uint4 h;
    h.x = cvt2(f0.x, f0.y);
    h.y = cvt2(f0.z, f0.w);
    h.z = cvt2(f1.x, f1.y);
    h.w = cvt2(f1.z, f1.w);
    *(uint4*)&g_Xh[i] = h;
}

// ---------------------------------------------------------------------------
// GEMM: CTA tile 128(M) x 128(N), K=768 in 12 stages of 64 halves.
// cp.async 3-stage pipeline, 8 warps of 32x64, mma.sync m16n8k16 fp16->fp32.
// ---------------------------------------------------------------------------
__global__ void __launch_bounds__(256, 2)
gemm_kernel(float* __restrict__ out) {
    extern __shared__ __align__(1024) char sm[];
    const uint32_t smb = (uint32_t)__cvta_generic_to_shared(sm);

    const int tid   = threadIdx.x;
    const int mtile = blockIdx.x;   // 0..31
    const int ntile = blockIdx.y;   // 0..1
    const int ib    = blockIdx.z;   // 0..63
    const int mrow0 = mtile * 128;
    const int brow0 = ntile * 128;

    const int warp = tid >> 5;
    const int lane = tid & 31;
    const int mw = warp >> 1;             // M offset mw*32
    const int nw = warp & 1;              // N offset nw*64
    const int g  = lane >> 2;
    const int tg = lane & 3;
    const int lr = (lane & 7) + ((lane >> 3) & 1) * 8;
    const int lk = (lane >> 4) & 1;

    // per-thread cp.async source mapping: 4 chunks of 16B for A and B each
    const int c_row = tid >> 3;           // base row 0..31 (4 passes of 32)
    const int c_seg = tid & 7;            // 16B segment within 128B row

    float acc[2][8][4];
#pragma unroll
    for (int a = 0; a < 2; a++)
#pragma unroll
        for (int b = 0; b < 8; b++)
#pragma unroll
            for (int c = 0; c < 4; c++) acc[a][b][c] = 0.f;

    auto issue_stage = [&](int s, int it) {
        int chunk = it >> 2;
        int bc = (ib + chunk + NBLK - 1) & (NBLK - 1);
        const __half* asrc = g_Xh + (size_t)mrow0 * OUTW + bc * P + (it & 3) * KT;
        const __half* bsrc = g_Wcvt + ((size_t)ib * P + brow0) * KDIM + it * KT;
        uint32_t ab = smb + SM_A(s);
        uint32_t bb = smb + SM_B(s);
#pragma unroll
        for (int p2 = 0; p2 < 4; p2++) {
            int row = c_row + p2 * 32;
            uint32_t off = (uint32_t)(row * 128 + ((c_seg * 16) ^ ((row & 7) << 4)));
            cp16(ab + off, asrc + (size_t)row * OUTW + c_seg * 8);
            cp16(bb + off, bsrc + (size_t)row * KDIM + c_seg * 8);
        }
    };

    auto mma_stage = [&](int buf) {
        uint32_t sa = smb + SM_A(buf);
        const char* sbp = sm + SM_B(buf);
#pragma unroll
        for (int ks = 0; ks < 4; ks++) {
            uint32_t af[2][4];
#pragma unroll
            for (int mt = 0; mt < 2; mt++) {
                int row = mw * 32 + mt * 16 + lr;
                uint32_t addr = sa + (uint32_t)(row * 128 + ((ks * 32 + lk * 16) ^ ((row & 7) << 4)));
                asm volatile("ldmatrix.sync.aligned.m8n8.x4.shared.b16 {%0,%1,%2,%3}, [%4];"
                             : "=r"(af[mt][0]), "=r"(af[mt][1]), "=r"(af[mt][2]), "=r"(af[mt][3])
                             : "r"(addr));
            }
            uint32_t bf[8][2];
#pragma unroll
            for (int nt = 0; nt < 8; nt++) {
                int row = nw * 64 + nt * 8 + g;
                int kb = ks * 32 + tg * 4;
                int sw = (row & 7) << 4;
                bf[nt][0] = *(const uint32_t*)(sbp + row * 128 + (kb ^ sw));
                bf[nt][1] = *(const uint32_t*)(sbp + row * 128 + ((kb + 16) ^ sw));
            }
#pragma unroll
            for (int mt = 0; mt < 2; mt++)
#pragma unroll
                for (int nt = 0; nt < 8; nt++)
                    asm volatile(
                        "mma.sync.aligned.m16n8k16.row.col.f32.f16.f16.f32 "
                        "{%0,%1,%2,%3}, {%4,%5,%6,%7}, {%8,%9}, {%0,%1,%2,%3};"
                        : "+f"(acc[mt][nt][0]), "+f"(acc[mt][nt][1]),
                          "+f"(acc[mt][nt][2]), "+f"(acc[mt][nt][3])
                        : "r"(af[mt][0]), "r"(af[mt][1]), "r"(af[mt][2]), "r"(af[mt][3]),
                          "r"(bf[nt][0]), "r"(bf[nt][1]));
        }
    };

    // ---- prologue: fill the 3-stage pipe ----
    issue_stage(0, 0); asm volatile("cp.async.commit_group;");
    issue_stage(1, 1); asm volatile("cp.async.commit_group;");
    issue_stage(2, 2); asm volatile("cp.async.commit_group;");

    // ---- mainloop ----
    for (int it = 0; it < NSTAGE_K; ++it) {
        asm volatile("cp.async.wait_group 2;");
        __syncthreads();
        mma_stage(it % NBUF);
        __syncthreads();
        if (it + NBUF < NSTAGE_K) issue_stage((it + NBUF) % NBUF, it + NBUF);
        asm volatile("cp.async.commit_group;");   // always commit to keep counts aligned
    }

    // ---- epilogue: direct fp32 stores ----
#pragma unroll
    for (int mt = 0; mt < 2; mt++) {
#pragma unroll
        for (int nt = 0; nt < 8; nt++) {
            int row = mrow0 + mw * 32 + mt * 16 + g;
            int col = ib * P + brow0 + nw * 64 + nt * 8 + tg * 2;
            *(float2*)&out[(size_t)row * OUTW + col] =
                make_float2(acc[mt][nt][0], acc[mt][nt][1]);
            *(float2*)&out[(size_t)(row + 8) * OUTW + col] =
                make_float2(acc[mt][nt][2], acc[mt][nt][3]);
        }
    }
}

extern "C" void kernel_launch(void* const* d_in, const int* in_sizes, int n_in,
                              void* d_out, int out_size) {
    const float* x   = (const float*)d_in[0];
    const float* Wd  = (const float*)d_in[1];
    const float* Wu  = (const float*)d_in[2];
    const float* Wl  = (const float*)d_in[3];
    const float* Wtr = (const float*)d_in[4];
    const float* Wbl = (const float*)d_in[5];
    float* out = (float*)d_out;

    cudaFuncSetAttribute(gemm_kernel, cudaFuncAttributeMaxDynamicSharedMemorySize, SM_TOTAL);

    // 1) weights -> fp16 band layout
    cvt_w_kernel<<<(NBLK * P * (KDIM / 2)) / 256, 256>>>(Wd, Wu, Wl, Wtr, Wbl);
    // 2) x -> fp16
    cvt_x_kernel<<<(int)(((size_t)ROWS * OUTW / 8) / 256), 256>>>(x);
    // 3) band GEMM
    dim3 grid(32, 2, NBLK);
    gemm_kernel<<<grid, 256, SM_TOTAL>>>(out);
}

// round 7
// speedup vs baseline: 1.6873x; 1.0751x over previous
#include <cuda_runtime.h>
#include <cuda_fp16.h>
#include <cstdint>

// ---------------- problem constants ----------------
#define NBLK 64
#define P    256
#define ROWS 4096
#define KDIM 768         // 3*P
#define OUTW 16384       // NBLK*P
#define KT   64          // k halves per stage (128B rows, SW128-style swizzle)
#define NSTAGE_K 12      // KDIM / KT
#define NBUF 3           // pipeline depth

// smem: per stage A 16KB + B 16KB
#define STG_BYTES 32768
#define SM_A(s) ((s) * STG_BYTES)
#define SM_B(s) ((s) * STG_BYTES + 16384)
#define SM_TOTAL (NBUF * STG_BYTES)   // 96KB

// fp16 band weights [i][n=256][k=768] and fp16 copy of x
__device__ __align__(16) __half g_Wcvt[(size_t)NBLK * P * KDIM];
__device__ __align__(16) __half g_Xh[(size_t)ROWS * OUTW];

__device__ __forceinline__ uint32_t cvt2(float a, float b) {
    __half2 h = __float22half2_rn(make_float2(a, b));
    return *(uint32_t*)&h;
}
__device__ __forceinline__ void cp16(uint32_t dst, const void* src) {
    asm volatile("cp.async.cg.shared.global [%0], [%1], 16;" :: "r"(dst), "l"(src));
}

// ---------------------------------------------------------------------------
// Weight gather + fp32->fp16 convert into band layout [i][n][k].
// ---------------------------------------------------------------------------
__global__ void cvt_w_kernel(const float* __restrict__ Wd, const float* __restrict__ Wu,
                             const float* __restrict__ Wl, const float* __restrict__ Wtr,
                             const float* __restrict__ Wbl) {
    int idx = blockIdx.x * blockDim.x + threadIdx.x;   // 64*256*384 (half2 units)
    int k2 = idx % (KDIM / 2);
    int n  = (idx / (KDIM / 2)) % P;
    int i  = idx / ((KDIM / 2) * P);
    int kg = k2 * 2;
    int chunk = kg >> 8;
    int p = kg & 255;
    const float* W;
    if (chunk == 0)      W = (i == 0)        ? Wtr : Wl + (size_t)(i - 1) * P * P;
    else if (chunk == 1) W = Wd + (size_t)i * P * P;
    else                 W = (i == NBLK - 1) ? Wbl : Wu + (size_t)i * P * P;
    ((uint32_t*)g_Wcvt)[idx] = cvt2(W[n * P + p], W[n * P + p + 1]);
}

// ---------------------------------------------------------------------------
// x fp32 -> fp16 (one pass)
// ---------------------------------------------------------------------------
__global__ void cvt_x_kernel(const float* __restrict__ x) {
    size_t i = ((size_t)blockIdx.x * 256 + threadIdx.x) * 8;
    float4 f0 = *(const float4*)(x + i);
    float4 f1 = *(const float4*)(x + i + 4);
    uint4 h;
    h.x = cvt2(f0.x, f0.y);
    h.y = cvt2(f0.z, f0.w);
    h.z = cvt2(f1.x, f1.y);
    h.w = cvt2(f1.z, f1.w);
    *(uint4*)&g_Xh[i] = h;
}

// ---------------------------------------------------------------------------
// GEMM: CTA tile 128(M) x 128(N), K=768 in 12 stages of 64 halves.
// cp.async 3-stage pipeline, 8 warps of 32x64, mma.sync m16n8k16 fp16->fp32.
// B fragments via ldmatrix.x4 (two n-tiles per load).
// ---------------------------------------------------------------------------
__global__ void __launch_bounds__(256, 2)
gemm_kernel(float* __restrict__ out) {
    extern __shared__ __align__(1024) char sm[];
    const uint32_t smb = (uint32_t)__cvta_generic_to_shared(sm);

    const int tid   = threadIdx.x;
    const int mtile = blockIdx.x;   // 0..31
    const int ntile = blockIdx.y;   // 0..1
    const int ib    = blockIdx.z;   // 0..63
    const int mrow0 = mtile * 128;
    const int brow0 = ntile * 128;

    const int warp = tid >> 5;
    const int lane = tid & 31;
    const int mw = warp >> 1;             // M offset mw*32
    const int nw = warp & 1;              // N offset nw*64
    const int g  = lane >> 2;
    const int tg = lane & 3;
    const int lr = (lane & 7) + ((lane >> 3) & 1) * 8;
    const int lk = (lane >> 4) & 1;
    // ldmatrix.x4 B addressing: quadrant q (0..3), row-in-matrix r (0..7)
    const int bq = lane >> 3;
    const int br = lane & 7;

    // per-thread cp.async source mapping: 4 chunks of 16B for A and B each
    const int c_row = tid >> 3;           // base row 0..31 (4 passes of 32)
    const int c_seg = tid & 7;            // 16B segment within 128B row

    float acc[2][8][4];
#pragma unroll
    for (int a = 0; a < 2; a++)
#pragma unroll
        for (int b = 0; b < 8; b++)
#pragma unroll
            for (int c = 0; c < 4; c++) acc[a][b][c] = 0.f;

    auto issue_stage = [&](int s, int it) {
        int chunk = it >> 2;
        int bc = (ib + chunk + NBLK - 1) & (NBLK - 1);
        const __half* asrc = g_Xh + (size_t)mrow0 * OUTW + bc * P + (it & 3) * KT;
        const __half* bsrc = g_Wcvt + ((size_t)ib * P + brow0) * KDIM + it * KT;
        uint32_t ab = smb + SM_A(s);
        uint32_t bb = smb + SM_B(s);
#pragma unroll
        for (int p2 = 0; p2 < 4; p2++) {
            int row = c_row + p2 * 32;
            uint32_t off = (uint32_t)(row * 128 + ((c_seg * 16) ^ ((row & 7) << 4)));
            cp16(ab + off, asrc + (size_t)row * OUTW + c_seg * 8);
            cp16(bb + off, bsrc + (size_t)row * KDIM + c_seg * 8);
        }
    };

    auto mma_stage = [&](int buf) {
        uint32_t sa = smb + SM_A(buf);
        uint32_t sb = smb + SM_B(buf);
#pragma unroll
        for (int ks = 0; ks < 4; ks++) {
            uint32_t af[2][4];
#pragma unroll
            for (int mt = 0; mt < 2; mt++) {
                int row = mw * 32 + mt * 16 + lr;
                uint32_t addr = sa + (uint32_t)(row * 128 + ((ks * 32 + lk * 16) ^ ((row & 7) << 4)));
                asm volatile("ldmatrix.sync.aligned.m8n8.x4.shared.b16 {%0,%1,%2,%3}, [%4];"
                             : "=r"(af[mt][0]), "=r"(af[mt][1]), "=r"(af[mt][2]), "=r"(af[mt][3])
                             : "r"(addr));
            }
            // B via ldmatrix.x4: m0 = n-rows(+0..7)@k0, m1 = same rows@k8,
            // m2 = rows+8@k0, m3 = rows+8@k8  -> fragments for 2 n-tiles
            uint32_t bf[8][2];
#pragma unroll
            for (int np = 0; np < 4; np++) {
                int row  = nw * 64 + np * 16 + ((bq >> 1) << 3) + br;
                int koff = ks * 32 + ((bq & 1) << 4);
                uint32_t addr = sb + (uint32_t)(row * 128 + (koff ^ ((row & 7) << 4)));
                asm volatile("ldmatrix.sync.aligned.m8n8.x4.shared.b16 {%0,%1,%2,%3}, [%4];"
                             : "=r"(bf[np * 2][0]), "=r"(bf[np * 2][1]),
                               "=r"(bf[np * 2 + 1][0]), "=r"(bf[np * 2 + 1][1])
                             : "r"(addr));
            }
#pragma unroll
            for (int mt = 0; mt < 2; mt++)
#pragma unroll
                for (int nt = 0; nt < 8; nt++)
                    asm volatile(
                        "mma.sync.aligned.m16n8k16.row.col.f32.f16.f16.f32 "
                        "{%0,%1,%2,%3}, {%4,%5,%6,%7}, {%8,%9}, {%0,%1,%2,%3};"
                        : "+f"(acc[mt][nt][0]), "+f"(acc[mt][nt][1]),
                          "+f"(acc[mt][nt][2]), "+f"(acc[mt][nt][3])
                        : "r"(af[mt][0]), "r"(af[mt][1]), "r"(af[mt][2]), "r"(af[mt][3]),
                          "r"(bf[nt][0]), "r"(bf[nt][1]));
        }
    };

    // ---- prologue: fill the 3-stage pipe ----
    issue_stage(0, 0); asm volatile("cp.async.commit_group;");
    issue_stage(1, 1); asm volatile("cp.async.commit_group;");
    issue_stage(2, 2); asm volatile("cp.async.commit_group;");

    // ---- mainloop ----
    for (int it = 0; it < NSTAGE_K; ++it) {
        asm volatile("cp.async.wait_group 2;");
        __syncthreads();
        mma_stage(it % NBUF);
        __syncthreads();
        if (it + NBUF < NSTAGE_K) issue_stage((it + NBUF) % NBUF, it + NBUF);
        asm volatile("cp.async.commit_group;");   // always commit to keep counts aligned
    }

    // ---- epilogue: direct fp32 stores ----
#pragma unroll
    for (int mt = 0; mt < 2; mt++) {
#pragma unroll
        for (int nt = 0; nt < 8; nt++) {
            int row = mrow0 + mw * 32 + mt * 16 + g;
            int col = ib * P + brow0 + nw * 64 + nt * 8 + tg * 2;
            *(float2*)&out[(size_t)row * OUTW + col] =
                make_float2(acc[mt][nt][0], acc[mt][nt][1]);
            *(float2*)&out[(size_t)(row + 8) * OUTW + col] =
                make_float2(acc[mt][nt][2], acc[mt][nt][3]);
        }
    }
}

extern "C" void kernel_launch(void* const* d_in, const int* in_sizes, int n_in,
                              void* d_out, int out_size) {
    const float* x   = (const float*)d_in[0];
    const float* Wd  = (const float*)d_in[1];
    const float* Wu  = (const float*)d_in[2];
    const float* Wl  = (const float*)d_in[3];
    const float* Wtr = (const float*)d_in[4];
    const float* Wbl = (const float*)d_in[5];
    float* out = (float*)d_out;

    cudaFuncSetAttribute(gemm_kernel, cudaFuncAttributeMaxDynamicSharedMemorySize, SM_TOTAL);

    // 1) weights -> fp16 band layout
    cvt_w_kernel<<<(NBLK * P * (KDIM / 2)) / 256, 256>>>(Wd, Wu, Wl, Wtr, Wbl);
    // 2) x -> fp16
    cvt_x_kernel<<<(int)(((size_t)ROWS * OUTW / 8) / 256), 256>>>(x);
    // 3) band GEMM
    dim3 grid(32, 2, NBLK);
    gemm_kernel<<<grid, 256, SM_TOTAL>>>(out);
}